// round 2
// baseline (speedup 1.0000x reference)
#include <cuda_runtime.h>

// Problem constants (fixed by the dataset)
static constexpr int B = 4096;
static constexpr int K = 1024;
static constexpr int C = 10;
static constexpr int M = 19;

// Tiling
static constexpr int NB = 32;             // batches per block (warp-lane dimension)
static constexpr int NC = 8;              // k-chunks per block
static constexpr int THREADS = NB * NC;   // 256
static constexpr int KCHUNK = K / NC;     // 128 samples per thread

// SMEM padding: 101 and 21 are coprime with 32 -> distinct lane base banks
static constexpr int TPAD = 101;          // product-table row stride
static constexpr int BPAD = 21;           // private bin row stride

__global__ __launch_bounds__(THREADS, 1)
void ised_kernel(const float* __restrict__ x1,
                 const float* __restrict__ x2,
                 const int*   __restrict__ idx1,
                 const int*   __restrict__ idx2,
                 float*       __restrict__ out)
{
    __shared__ float table[NB * TPAD];        // per-b 10x10 product table
    __shared__ float bins[THREADS * BPAD];    // per-thread private 19 bins

    const int tid = threadIdx.x;
    const int b0  = blockIdx.x * NB;

    // ---- Build per-b product tables: table[bl][i*10+j] = x1[b,i]*x2[b,j] ----
    // 32*100 = 3200 entries over 256 threads
    for (int e = tid; e < NB * 100; e += THREADS) {
        const int bl = e / 100;
        const int ij = e - bl * 100;
        const int i  = ij / 10;
        const int j  = ij - i * 10;
        const float a = __ldg(&x1[(b0 + bl) * C + i]);
        const float c = __ldg(&x2[(b0 + bl) * C + j]);
        table[bl * TPAD + ij] = a * c;
    }

    // ---- Zero private bins ----
    for (int e = tid; e < THREADS * BPAD; e += THREADS) {
        bins[e] = 0.0f;
    }
    __syncthreads();

    // ---- Main accumulation loop ----
    // tid = kc*NB + bl : lanes within a warp have consecutive b -> coalesced idx loads
    const int bl = tid & (NB - 1);
    const int kc = tid >> 5;               // NB == 32
    const int b  = b0 + bl;

    const int* __restrict__ p1 = idx1 + (size_t)kc * KCHUNK * B + b;
    const int* __restrict__ p2 = idx2 + (size_t)kc * KCHUNK * B + b;
    float* __restrict__ myb = bins + tid * BPAD;
    const float* __restrict__ myt = table + bl * TPAD;

    #pragma unroll 4
    for (int k = 0; k < KCHUNK; k++) {
        const int i1 = __ldg(&p1[(size_t)k * B]);
        const int i2 = __ldg(&p2[(size_t)k * B]);
        const float p = myt[i1 * 10 + i2];
        myb[i1 + i2] += p;
    }
    __syncthreads();

    // ---- Reduce NC partial rows per b, L2-normalize, write out ----
    if (tid < NB) {
        float s[M];
        float sq = 0.0f;
        #pragma unroll
        for (int m = 0; m < M; m++) {
            float v = 0.0f;
            #pragma unroll
            for (int c = 0; c < NC; c++) {
                v += bins[(c * NB + tid) * BPAD + m];
            }
            s[m] = v;
            sq += v * v;
        }
        const float norm  = sqrtf(sq);
        const float scale = 1.0f / fmaxf(norm, 1e-12f);
        float* __restrict__ orow = out + (size_t)(b0 + tid) * M;
        #pragma unroll
        for (int m = 0; m < M; m++) {
            orow[m] = s[m] * scale;
        }
    }
}

extern "C" void kernel_launch(void* const* d_in, const int* in_sizes, int n_in,
                              void* d_out, int out_size)
{
    const float* x1   = (const float*)d_in[0];   // [B, C]
    const float* x2   = (const float*)d_in[1];   // [B, C]
    const int*   idx1 = (const int*)d_in[2];     // [K, B]
    const int*   idx2 = (const int*)d_in[3];     // [K, B]
    float*       out  = (float*)d_out;           // [B, M]

    (void)in_sizes; (void)n_in; (void)out_size;

    ised_kernel<<<B / NB, THREADS>>>(x1, x2, idx1, idx2, out);
}

// round 3
// speedup vs baseline: 1.0695x; 1.0695x over previous
#include <cuda_runtime.h>

// Problem constants (fixed by the dataset)
static constexpr int B = 4096;
static constexpr int K = 1024;
static constexpr int C = 10;
static constexpr int M = 19;

// Tiling: grid = B/NB = 512 blocks -> ~3.5 blocks/SM on 148 SMs,
// 256 thr & ~25KB smem -> 4 resident blocks/SM = 32 warps (50% occ)
static constexpr int NB = 8;              // batches per block
static constexpr int NC = 32;             // k-chunks per block
static constexpr int THREADS = NB * NC;   // 256
static constexpr int KCHUNK = K / NC;     // 32 samples per thread

static constexpr int TPAD = 101;          // product-table row stride (coprime w/ 32)
static constexpr int BPAD = 21;           // private bin row stride (odd -> bank permute)

__global__ __launch_bounds__(THREADS)
void ised_kernel(const float* __restrict__ x1,
                 const float* __restrict__ x2,
                 const int*   __restrict__ idx1,
                 const int*   __restrict__ idx2,
                 float*       __restrict__ out)
{
    __shared__ float table[NB * TPAD];        // per-b 10x10 product table
    __shared__ float bins[THREADS * BPAD];    // per-thread private 19 bins
    __shared__ float rowsum[NB][M + 1];       // reduced per-b bins

    const int tid = threadIdx.x;
    const int b0  = blockIdx.x * NB;

    // ---- Build per-b product tables: table[bl][i*10+j] = x1[b,i]*x2[b,j] ----
    // NB*100 = 800 entries over 256 threads
    for (int e = tid; e < NB * 100; e += THREADS) {
        const int bl = e / 100;
        const int ij = e - bl * 100;
        const int i  = ij / 10;
        const int j  = ij - i * 10;
        const float a = __ldg(&x1[(b0 + bl) * C + i]);
        const float c = __ldg(&x2[(b0 + bl) * C + j]);
        table[bl * TPAD + ij] = a * c;
    }

    // ---- Zero private bins ----
    for (int e = tid; e < THREADS * BPAD; e += THREADS) {
        bins[e] = 0.0f;
    }
    __syncthreads();

    // ---- Main accumulation loop ----
    // tid = kc*NB + bl : 8 consecutive b per lane-group -> full 32B sectors
    const int bl = tid & (NB - 1);
    const int kc = tid / NB;
    const int b  = b0 + bl;

    const int* __restrict__ p1 = idx1 + (size_t)kc * KCHUNK * B + b;
    const int* __restrict__ p2 = idx2 + (size_t)kc * KCHUNK * B + b;
    float* __restrict__ myb = bins + tid * BPAD;
    const float* __restrict__ myt = table + bl * TPAD;

    #pragma unroll 4
    for (int k = 0; k < KCHUNK; k++) {
        const int i1 = __ldg(&p1[(size_t)k * B]);
        const int i2 = __ldg(&p2[(size_t)k * B]);
        const float p = myt[i1 * 10 + i2];
        myb[i1 + i2] += p;
    }
    __syncthreads();

    // ---- Parallel reduce NC partial rows per (b, m): NB*M = 152 threads ----
    for (int e = tid; e < NB * M; e += THREADS) {
        const int rbl = e / M;
        const int m   = e - rbl * M;
        float v = 0.0f;
        #pragma unroll
        for (int c = 0; c < NC; c++) {
            v += bins[(c * NB + rbl) * BPAD + m];
        }
        rowsum[rbl][m] = v;
    }
    __syncthreads();

    // ---- L2-normalize and write out ----
    if (tid < NB) {
        float sq = 0.0f;
        #pragma unroll
        for (int m = 0; m < M; m++) {
            const float v = rowsum[tid][m];
            sq += v * v;
        }
        const float norm  = sqrtf(sq);
        const float scale = 1.0f / fmaxf(norm, 1e-12f);
        float* __restrict__ orow = out + (size_t)(b0 + tid) * M;
        #pragma unroll
        for (int m = 0; m < M; m++) {
            orow[m] = rowsum[tid][m] * scale;
        }
    }
}

extern "C" void kernel_launch(void* const* d_in, const int* in_sizes, int n_in,
                              void* d_out, int out_size)
{
    const float* x1   = (const float*)d_in[0];   // [B, C]
    const float* x2   = (const float*)d_in[1];   // [B, C]
    const int*   idx1 = (const int*)d_in[2];     // [K, B]
    const int*   idx2 = (const int*)d_in[3];     // [K, B]
    float*       out  = (float*)d_out;           // [B, M]

    (void)in_sizes; (void)n_in; (void)out_size;

    ised_kernel<<<B / NB, THREADS>>>(x1, x2, idx1, idx2, out);
}